// round 7
// baseline (speedup 1.0000x reference)
#include <cuda_runtime.h>

// BiasedFeatureDropout: out = x * 1.25 * (threefry_bits(i) < T(channel))
// Bit-exact JAX partitionable threefry-2x32, keys (0,1), counter hi=0.
//
// Round-7 build: ALL 20 rotates moved off the alu pipe via IMAD.WIDE
// (rot(x,r) = lo|hi of x * (1<<r)) + single fused LOP3 (lo|hi)^x0.
// Explicit 4-stream SoA interleave (structural ILP=4) at 4 elems/thread.
// alu/elem drops ~45 -> ~26; kernel should become issue-bound.

static constexpr unsigned KS2      = 0x1BD11BDBu;   // 0 ^ 1 ^ 0x1BD11BDA
static constexpr unsigned HW       = 56u * 56u;     // 3136, divisible by 4
static constexpr unsigned THR_BIAS = 858993664u;    // keep=0.2f
static constexpr unsigned THR_REG  = 3435974144u;   // keep=0.8f

// a*one + c -> IMAD (fma pipe); 'one' is a runtime kernel arg (==1)
__device__ __forceinline__ unsigned madd(unsigned a, unsigned one, unsigned c) {
    unsigned r;
    asm("mad.lo.u32 %0, %1, %2, %3;" : "=r"(r) : "r"(a), "r"(one), "r"(c));
    return r;
}

// quad wide round: x0 += x1 (IMAD); x1 = rot(x1) ^ x0 (IMAD.WIDE + LOP3)
#define QRW(pp)                                                         \
    _Pragma("unroll")                                                   \
    for (int s = 0; s < 4; s++) {                                       \
        x0[s] = madd(x1[s], one, x0[s]);                                \
        unsigned long long t = (unsigned long long)x1[s] * (pp);        \
        x1[s] = ((unsigned)t | (unsigned)(t >> 32)) ^ x0[s];            \
    }
// quad wide round with folded x0 key-injection (3-input IADD3, alu)
#define QRWF(pp, a)                                                     \
    _Pragma("unroll")                                                   \
    for (int s = 0; s < 4; s++) {                                       \
        x0[s] = x0[s] + x1[s] + (a);                                    \
        unsigned long long t = (unsigned long long)x1[s] * (pp);        \
        x1[s] = ((unsigned)t | (unsigned)(t >> 32)) ^ x0[s];            \
    }
// quad x1-side key injection (IMAD, fma)
#define QINJ(a)                                                         \
    _Pragma("unroll")                                                   \
    for (int s = 0; s < 4; s++) x1[s] = madd(x1[s], one, (a));

__global__ __launch_bounds__(256)
void biased_dropout_kernel(const float4* __restrict__ x,
                           float4* __restrict__ y,
                           unsigned one,            // always 1, opaque to ptxas
                           unsigned n_vec) {
    unsigned t = blockIdx.x * blockDim.x + threadIdx.x;
    if (t >= n_vec) return;

    unsigned base = t * 4u;
    unsigned ch  = (base / HW) & 255u;               // HW % 4 == 0
    unsigned thr = (ch < 32u) ? THR_BIAS : THR_REG;

    // runtime-opaque rotation multipliers
    unsigned p6  = one << 6,  p13 = one << 13, p15 = one << 15,
             p16 = one << 16, p17 = one << 17, p24 = one << 24,
             p26 = one << 26, p29 = one << 29;

    float4 v = x[t];

    unsigned x0[4], x1[4];
#pragma unroll
    for (int s = 0; s < 4; s++) {
        x1[s] = madd(base, one, (unsigned)(s + 1));  // ctr + ks1(=1)
        x0[s] = x1[s];                               // r1 add folds (x0 init 0)
        unsigned long long tt = (unsigned long long)x1[s] * p13;   // r1 rot13
        x1[s] = ((unsigned)tt | (unsigned)(tt >> 32)) ^ x0[s];
    }
    QRW(p15) QRW(p26) QRW(p6)        // r2-r4
    QINJ(KS2 + 1u)                   // inj1: x1 += ks2+1
    QRWF(p17, 1u)                    // r5  (x0 += ks1=1 folded)
    QRW(p29) QRW(p16) QRW(p24)       // r6-r8
    QINJ(2u)                         // inj2: x1 += ks0+2
    QRWF(p13, KS2)                   // r9  (x0 += ks2 folded)
    QRW(p15) QRW(p26) QRW(p6)        // r10-r12
    QINJ(4u)                         // inj3: x1 += ks1+3
    QRW(p17)                         // r13 (x0 inj = ks0 = 0, free)
    QRW(p29) QRW(p16) QRW(p24)       // r14-r16
    QINJ(KS2 + 4u)                   // inj4: x1 += ks2+4
    QRWF(p13, 1u)                    // r17 (x0 += ks1=1 folded)
    QRW(p15) QRW(p26) QRW(p6)        // r18-r20

    unsigned b[4];
#pragma unroll
    for (int s = 0; s < 4; s++)      // final: (x0+ks2) ^ (x1+ks0+5)
        b[s] = (x0[s] + KS2) ^ madd(x1[s], one, 5u);

    float4 o;
    o.x = (b[0] < thr) ? v.x * 1.25f : 0.0f;
    o.y = (b[1] < thr) ? v.y * 1.25f : 0.0f;
    o.z = (b[2] < thr) ? v.z * 1.25f : 0.0f;
    o.w = (b[3] < thr) ? v.w * 1.25f : 0.0f;

    y[t] = o;
}

extern "C" void kernel_launch(void* const* d_in, const int* in_sizes, int n_in,
                              void* d_out, int out_size) {
    (void)n_in; (void)out_size;
    const float4* x = (const float4*)d_in[0];
    float4* y = (float4*)d_out;
    unsigned n = (unsigned)in_sizes[0];          // 51,380,224
    unsigned n_vec = n / 4u;                     // 12,845,056 (exact)
    unsigned blocks = (n_vec + 255u) / 256u;     // 50,176
    biased_dropout_kernel<<<blocks, 256>>>(x, y, 1u, n_vec);
}

// round 9
// speedup vs baseline: 1.4596x; 1.4596x over previous
#include <cuda_runtime.h>

// BiasedFeatureDropout: out = x * 1.25 * (threefry_bits(i) < T(channel))
// Bit-exact JAX partitionable threefry-2x32, keys (0,1), counter hi=0.
//
// Round-9 build (= round-8 candidate, re-bench after infra failure):
// R6 round structure (SHF/LOP3 rounds, PRMT for rot16/24, plain C++ adds
// -> ptxas alternates IMAD/IADD3 across pipes), plus:
//  - 8 elems/thread (8 independent hash streams)
//  - __launch_bounds__(256, 4): lifts ptxas's 32-reg full-occupancy cap to
//    64 regs so the 8 streams can actually stay live and interleave.
// Every prior build was pinned at <=32 regs -> streams serialized -> IPC 0.76.

static constexpr unsigned KS2      = 0x1BD11BDBu;   // 0 ^ 1 ^ 0x1BD11BDA
static constexpr unsigned HW       = 56u * 56u;     // 3136, divisible by 8
static constexpr unsigned THR_BIAS = 858993664u;    // keep=0.2f
static constexpr unsigned THR_REG  = 3435974144u;   // keep=0.8f

// SHF round: add + funnel-shift rotate + xor
#define RS(rr)      { x0 += x1; x1 = __funnelshift_l(x1, x1, (rr)) ^ x0; }
// SHF round with folded x0 key-injection (3-input add)
#define RSF(rr, a)  { x0 += x1 + (a); x1 = __funnelshift_l(x1, x1, (rr)) ^ x0; }
// PRMT round: rot16 sel=0x1032, rot24 sel=0x0321
#define RP(sel)     { x0 += x1; x1 = __byte_perm(x1, 0u, (sel)) ^ x0; }

__device__ __forceinline__ unsigned threefry_bits(unsigned ctr) {
    unsigned x0, x1;
    x1 = ctr + 1u;                               // x1 = ctr + ks1(=1)
    // r1 (rot13): x0 = 0 + x1 (free), x1 = rot13(x1) ^ x0
    x0 = x1;
    x1 = __funnelshift_l(x1, x1, 13) ^ x0;
    RS(15) RS(26) RS(6)                          // r2-r4
    x1 += KS2 + 1u;                              // inj1: x1 += ks2+1
    RSF(17, 1u)                                  // r5  (x0 += ks1=1 folded)
    RS(29)                                       // r6
    RP(0x1032u)                                  // r7  rot16
    RP(0x0321u)                                  // r8  rot24
    x1 += 2u;                                    // inj2: x1 += ks0+2
    RSF(13, KS2)                                 // r9  (x0 += ks2 folded)
    RS(15) RS(26) RS(6)                          // r10-r12
    x1 += 4u;                                    // inj3: x1 += ks1+3
    RS(17)                                       // r13 (x0 += ks0=0, free)
    RS(29)                                       // r14
    RP(0x1032u)                                  // r15 rot16
    RP(0x0321u)                                  // r16 rot24
    x1 += KS2 + 4u;                              // inj4: x1 += ks2+4
    RSF(13, 1u)                                  // r17 (x0 += ks1=1 folded)
    RS(15) RS(26) RS(6)                          // r18-r20
    // final: (x0 + ks2) ^ (x1 + ks0 + 5)
    return (x0 + KS2) ^ (x1 + 5u);
}

__global__ __launch_bounds__(256, 4)   // <=64 regs: let 8 streams stay live
void biased_dropout_kernel(const float4* __restrict__ x,
                           float4* __restrict__ y,
                           unsigned n_thr) {
    unsigned t = blockIdx.x * blockDim.x + threadIdx.x;
    if (t >= n_thr) return;

    unsigned base = t * 8u;
    unsigned ch  = (base / HW) & 255u;               // HW % 8 == 0
    unsigned thr = (ch < 32u) ? THR_BIAS : THR_REG;

    float4 v0 = x[2u * t];
    float4 v1 = x[2u * t + 1u];

    unsigned b[8];
#pragma unroll
    for (int i = 0; i < 8; i++)
        b[i] = threefry_bits(base + (unsigned)i);

    float4 o0, o1;
    o0.x = (b[0] < thr) ? v0.x * 1.25f : 0.0f;
    o0.y = (b[1] < thr) ? v0.y * 1.25f : 0.0f;
    o0.z = (b[2] < thr) ? v0.z * 1.25f : 0.0f;
    o0.w = (b[3] < thr) ? v0.w * 1.25f : 0.0f;
    o1.x = (b[4] < thr) ? v1.x * 1.25f : 0.0f;
    o1.y = (b[5] < thr) ? v1.y * 1.25f : 0.0f;
    o1.z = (b[6] < thr) ? v1.z * 1.25f : 0.0f;
    o1.w = (b[7] < thr) ? v1.w * 1.25f : 0.0f;

    y[2u * t]      = o0;
    y[2u * t + 1u] = o1;
}

extern "C" void kernel_launch(void* const* d_in, const int* in_sizes, int n_in,
                              void* d_out, int out_size) {
    (void)n_in; (void)out_size;
    const float4* x = (const float4*)d_in[0];
    float4* y = (float4*)d_out;
    unsigned n = (unsigned)in_sizes[0];          // 51,380,224
    unsigned n_thr = n / 8u;                     // 6,422,528 (exact)
    unsigned blocks = (n_thr + 255u) / 256u;     // 25,088
    biased_dropout_kernel<<<blocks, 256>>>(x, y, n_thr);
}